// round 4
// baseline (speedup 1.0000x reference)
#include <cuda_runtime.h>

#define BB 4096
#define TT 16
#define HH 768
#define AA 128
#define VV 16
#define LL 2
#define MTILE 32
#define KC 128
#define NC 128
#define XPAD 33
#define NTHREADS 512
#define MAXTILES 160

// ---- device-global scratch ----
__device__ int g_counts[VV];
__device__ int g_bins[VV * BB];
__device__ int g_ntiles;
__device__ int g_tiles[MAXTILES];

__global__ void va_zero_counts() {
    if (threadIdx.x < VV) g_counts[threadIdx.x] = 0;
}

__global__ void va_bin(const int* __restrict__ vids) {
    int b = blockIdx.x * blockDim.x + threadIdx.x;
    if (b < BB) {
        int v = vids[b];
        int slot = atomicAdd(&g_counts[v], 1);
        g_bins[v * BB + slot] = b;
    }
}

__global__ void va_build_tiles() {
    if (threadIdx.x == 0) {
        int t = 0;
        for (int v = 0; v < VV; v++) {
            int c = g_counts[v];
            for (int r0 = 0; r0 < c; r0 += MTILE)
                g_tiles[t++] = (v << 16) | (r0 / MTILE);
        }
        g_ntiles = t;
    }
}

// ---- f32x2 packed-FMA helpers ----
typedef unsigned long long u64t;

__device__ __forceinline__ u64t dup2(float x) {
    u64t r;
    asm("mov.b64 %0, {%1, %1};" : "=l"(r) : "f"(x));
    return r;
}
__device__ __forceinline__ u64t fma2(u64t a, u64t b, u64t c) {
    u64t d;
    asm("fma.rn.f32x2 %0, %1, %2, %3;" : "=l"(d) : "l"(a), "l"(b), "l"(c));
    return d;
}
__device__ __forceinline__ float2 upk(u64t d) {
    float2 f;
    asm("mov.b64 {%0, %1}, %2;" : "=f"(f.x), "=f"(f.y) : "l"(d));
    return f;
}

__device__ __forceinline__ float gelu_tanh(float x) {
    float x3 = x * x * x;
    float t = tanhf(0.7978845608028654f * (x + 0.044715f * x3));
    return 0.5f * x * (1.0f + t);
}

// smem: sXt[HH][XPAD] + sHt[AA][XPAD] + sW[128*128]
#define SMEM_FLOATS (HH * XPAD + AA * XPAD + 128 * 128)

extern "C" __global__ void __launch_bounds__(NTHREADS, 1)
va_main(const float* __restrict__ lh,
        const float* __restrict__ Wd, const float* __restrict__ bd,
        const float* __restrict__ Wu, const float* __restrict__ bu,
        const float* __restrict__ Wc, const float* __restrict__ bc,
        float* __restrict__ out) {
    extern __shared__ float smem[];
    float* sXt = smem;                    // [k][row], stride XPAD
    float* sHt = smem + HH * XPAD;        // [a][row], stride XPAD
    float* sW  = smem + HH * XPAD + AA * XPAD;   // [k][128]
    __shared__ int sB[MTILE];

    const int tid  = threadIdx.x;
    const int lane = tid & 31;            // row index within tile
    const int warp = tid >> 5;            // 0..15 -> col group of 8
    const int cg8  = warp * 8;

    const int ntiles = g_ntiles;

    for (int t = blockIdx.x; t < ntiles; t += gridDim.x) {
        const int info = g_tiles[t];
        const int v    = info >> 16;
        const int row0 = (info & 0xFFFF) * MTILE;
        const int cnt  = g_counts[v];

        if (tid < MTILE) {
            int gr = row0 + tid;
            sB[tid] = (gr < cnt) ? g_bins[v * BB + gr] : -1;
        }
        __syncthreads();

        // ---- GEMM1 stage-0 weight prefetch (overlaps gather) ----
        const float* Wdv = Wd + (size_t)v * HH * AA;
        float4 pf[8];
        #pragma unroll
        for (int q = 0; q < 8; q++)
            pf[q] = *(const float4*)(Wdv + (size_t)(q * NTHREADS + tid) * 4);

        // ---- gather 32 x rows (t=0) transposed into sXt ----
        // row varies fastest so smem stores are conflict-free
        for (int idx = tid; idx < MTILE * (HH / 4); idx += NTHREADS) {
            int r  = idx & 31;
            int k4 = idx >> 5;
            int b  = sB[r];
            float4 val = make_float4(0.f, 0.f, 0.f, 0.f);
            if (b >= 0)
                val = *(const float4*)(lh + (size_t)b * TT * HH + k4 * 4);
            sXt[(k4 * 4 + 0) * XPAD + r] = val.x;
            sXt[(k4 * 4 + 1) * XPAD + r] = val.y;
            sXt[(k4 * 4 + 2) * XPAD + r] = val.z;
            sXt[(k4 * 4 + 3) * XPAD + r] = val.w;
        }

        u64t acc1[4];
        acc1[0] = acc1[1] = acc1[2] = acc1[3] = 0ull;

        __syncthreads();   // sXt ready; sW free

        // ============ GEMM1: H[32][128] = X[32][768] @ Wd[v] ============
        for (int k0 = 0; k0 < HH; k0 += KC) {
            #pragma unroll
            for (int q = 0; q < 8; q++)
                *(float4*)(sW + (q * NTHREADS + tid) * 4) = pf[q];
            __syncthreads();
            if (k0 + KC < HH) {
                const float* src = Wdv + (size_t)(k0 + KC) * AA;
                #pragma unroll
                for (int q = 0; q < 8; q++)
                    pf[q] = *(const float4*)(src + (size_t)(q * NTHREADS + tid) * 4);
            }
            #pragma unroll 4
            for (int kk = 0; kk < KC; kk++) {
                float a = sXt[(k0 + kk) * XPAD + lane];
                double2 B0 = *(const double2*)(sW + kk * AA + cg8);
                double2 B1 = *(const double2*)(sW + kk * AA + cg8 + 4);
                u64t av = dup2(a);
                acc1[0] = fma2(av, __double_as_longlong(B0.x), acc1[0]);
                acc1[1] = fma2(av, __double_as_longlong(B0.y), acc1[1]);
                acc1[2] = fma2(av, __double_as_longlong(B1.x), acc1[2]);
                acc1[3] = fma2(av, __double_as_longlong(B1.y), acc1[3]);
            }
            __syncthreads();
        }

        // ---- GEMM2 stage-0 prefetch (overlaps gelu) ----
        const float* Wuv = Wu + (size_t)v * AA * HH;
        #pragma unroll
        for (int q = 0; q < 8; q++) {
            int idx4 = q * NTHREADS + tid;
            int a    = idx4 >> 5;
            int cc4  = idx4 & 31;
            pf[q] = *(const float4*)(Wuv + (size_t)a * HH + cc4 * 4);
        }

        // ---- bias + gelu -> sHt transposed ----
        {
            const float* bdv = bd + v * AA;
            #pragma unroll
            for (int j2 = 0; j2 < 4; j2++) {
                float2 f = upk(acc1[j2]);
                float g0 = gelu_tanh(f.x + __ldg(bdv + cg8 + 2 * j2));
                float g1 = gelu_tanh(f.y + __ldg(bdv + cg8 + 2 * j2 + 1));
                sHt[(cg8 + 2 * j2 + 0) * XPAD + lane] = g0;
                sHt[(cg8 + 2 * j2 + 1) * XPAD + lane] = g1;
            }
        }
        __syncthreads();

        // ====== GEMM2 (6 col-tiles of 128) + residual + classifier ======
        const float* buv = bu + v * HH;
        float out0 = 0.f, out1 = 0.f;

        for (int c0 = 0; c0 < HH; c0 += NC) {
            #pragma unroll
            for (int q = 0; q < 8; q++) {
                int idx4 = q * NTHREADS + tid;
                int a    = idx4 >> 5;
                int cc4  = idx4 & 31;
                *(float4*)(sW + a * NC + cc4 * 4) = pf[q];
            }
            __syncthreads();
            if (c0 + NC < HH) {
                #pragma unroll
                for (int q = 0; q < 8; q++) {
                    int idx4 = q * NTHREADS + tid;
                    int a    = idx4 >> 5;
                    int cc4  = idx4 & 31;
                    pf[q] = *(const float4*)(Wuv + (size_t)a * HH + (c0 + NC) + cc4 * 4);
                }
            }

            u64t acc2[4];
            acc2[0] = acc2[1] = acc2[2] = acc2[3] = 0ull;

            #pragma unroll 4
            for (int kk = 0; kk < AA; kk++) {
                float a = sHt[kk * XPAD + lane];
                double2 B0 = *(const double2*)(sW + kk * NC + cg8);
                double2 B1 = *(const double2*)(sW + kk * NC + cg8 + 4);
                u64t av = dup2(a);
                acc2[0] = fma2(av, __double_as_longlong(B0.x), acc2[0]);
                acc2[1] = fma2(av, __double_as_longlong(B0.y), acc2[1]);
                acc2[2] = fma2(av, __double_as_longlong(B1.x), acc2[2]);
                acc2[3] = fma2(av, __double_as_longlong(B1.y), acc2[3]);
            }

            // epilogue: adapted = x + u + bu; out += adapted * Wc^T
            #pragma unroll
            for (int j2 = 0; j2 < 4; j2++) {
                float2 u = upk(acc2[j2]);
                #pragma unroll
                for (int e = 0; e < 2; e++) {
                    int col = c0 + cg8 + 2 * j2 + e;
                    float uv = e ? u.y : u.x;
                    float ad = sXt[col * XPAD + lane] + uv + __ldg(buv + col);
                    out0 = fmaf(ad, __ldg(Wc + col), out0);
                    out1 = fmaf(ad, __ldg(Wc + HH + col), out1);
                }
            }
            __syncthreads();
        }

        // ---- reduce partial (row=lane) sums across 16 warps via smem ----
        float* sRed = sW;   // free after last sync
        sRed[(warp * MTILE + lane) * 2 + 0] = out0;
        sRed[(warp * MTILE + lane) * 2 + 1] = out1;
        __syncthreads();
        if (tid < MTILE * LL) {
            int row = tid >> 1;
            int l   = tid & 1;
            float s = __ldg(bc + l);
            #pragma unroll
            for (int w = 0; w < 16; w++)
                s += sRed[(w * MTILE + row) * 2 + l];
            int b = sB[row];
            if (b >= 0) out[b * LL + l] = s;
        }
        __syncthreads();
    }
}

extern "C" void kernel_launch(void* const* d_in, const int* in_sizes, int n_in,
                              void* d_out, int out_size) {
    const float* lh   = (const float*)d_in[0];
    const int*   vids = (const int*)d_in[2];
    const float* Wd   = (const float*)d_in[3];
    const float* bd   = (const float*)d_in[4];
    const float* Wu   = (const float*)d_in[5];
    const float* bu   = (const float*)d_in[6];
    const float* Wc   = (const float*)d_in[7];
    const float* bc   = (const float*)d_in[8];
    float* out = (float*)d_out;

    size_t smem_bytes = SMEM_FLOATS * sizeof(float);
    cudaFuncSetAttribute(va_main, cudaFuncAttributeMaxDynamicSharedMemorySize,
                         (int)smem_bytes);

    va_zero_counts<<<1, 32>>>();
    va_bin<<<BB / 256, 256>>>(vids);
    va_build_tiles<<<1, 32>>>();
    va_main<<<148, NTHREADS, smem_bytes>>>(lh, Wd, bd, Wu, bu, Wc, bc, out);
}

// round 6
// speedup vs baseline: 1.1921x; 1.1921x over previous
#include <cuda_runtime.h>

#define BB 4096
#define TT 16
#define HH 768
#define AA 128
#define VV 16
#define LL 2
#define MTILE 32
#define KC 128
#define XPAD 34
#define NTHREADS 256
#define MAXTILES 160

// ---- device-global scratch ----
__device__ int g_counts[VV];
__device__ int g_bins[VV * BB];
__device__ int g_ntiles;
__device__ int g_tiles[MAXTILES];
__device__ float g_Wc2[VV * AA * LL];   // [v][a][l] = sum_h Wu[v][a][h] * Wc[l][h]
__device__ float g_buc[VV * LL];        // [v][l]    = sum_h bu[v][h]    * Wc[l][h]

__global__ void va_zero_counts() {
    if (threadIdx.x < VV) g_counts[threadIdx.x] = 0;
}

__global__ void va_bin(const int* __restrict__ vids) {
    int b = blockIdx.x * blockDim.x + threadIdx.x;
    if (b < BB) {
        int v = vids[b];
        int slot = atomicAdd(&g_counts[v], 1);
        g_bins[v * BB + slot] = b;
    }
}

__global__ void va_build_tiles() {
    if (threadIdx.x == 0) {
        int t = 0;
        for (int v = 0; v < VV; v++) {
            int c = g_counts[v];
            for (int r0 = 0; r0 < c; r0 += MTILE)
                g_tiles[t++] = (v << 16) | (r0 / MTILE);
        }
        g_ntiles = t;
    }
}

// ---- fold the classifier through Wu:  Wc2[v] = Wu[v] @ Wc^T ----
__global__ void va_fold(const float* __restrict__ Wu,
                        const float* __restrict__ bu,
                        const float* __restrict__ Wc) {
    int v    = blockIdx.x;
    int warp = threadIdx.x >> 5;
    int lane = threadIdx.x & 31;

    for (int a = warp; a < AA; a += 8) {
        const float* row = Wu + ((size_t)v * AA + a) * HH;
        float s0 = 0.f, s1 = 0.f;
        for (int h = lane; h < HH; h += 32) {
            float w = row[h];
            s0 = fmaf(w, Wc[h],      s0);
            s1 = fmaf(w, Wc[HH + h], s1);
        }
        #pragma unroll
        for (int off = 16; off; off >>= 1) {
            s0 += __shfl_xor_sync(0xFFFFFFFFu, s0, off);
            s1 += __shfl_xor_sync(0xFFFFFFFFu, s1, off);
        }
        if (lane == 0) {
            g_Wc2[(v * AA + a) * 2 + 0] = s0;
            g_Wc2[(v * AA + a) * 2 + 1] = s1;
        }
    }
    if (warp == 0) {
        float s0 = 0.f, s1 = 0.f;
        for (int h = lane; h < HH; h += 32) {
            float b = bu[v * HH + h];
            s0 = fmaf(b, Wc[h],      s0);
            s1 = fmaf(b, Wc[HH + h], s1);
        }
        #pragma unroll
        for (int off = 16; off; off >>= 1) {
            s0 += __shfl_xor_sync(0xFFFFFFFFu, s0, off);
            s1 += __shfl_xor_sync(0xFFFFFFFFu, s1, off);
        }
        if (lane == 0) {
            g_buc[v * 2 + 0] = s0;
            g_buc[v * 2 + 1] = s1;
        }
    }
}

// ---- f32x2 packed-FMA helpers ----
typedef unsigned long long u64t;

__device__ __forceinline__ u64t dup2(float x) {
    u64t r;
    asm("mov.b64 %0, {%1, %1};" : "=l"(r) : "f"(x));
    return r;
}
__device__ __forceinline__ u64t fma2(u64t a, u64t b, u64t c) {
    u64t d;
    asm("fma.rn.f32x2 %0, %1, %2, %3;" : "=l"(d) : "l"(a), "l"(b), "l"(c));
    return d;
}
__device__ __forceinline__ float2 upk(u64t d) {
    float2 f;
    asm("mov.b64 {%0, %1}, %2;" : "=f"(f.x), "=f"(f.y) : "l"(d));
    return f;
}

__device__ __forceinline__ float gelu_tanh(float x) {
    float x3 = x * x * x;
    float t = tanhf(0.7978845608028654f * (x + 0.044715f * x3));
    return 0.5f * x * (1.0f + t);
}

// smem: sXt[HH][XPAD] + sWc[HH*LL] + sWc2[256] + sW[KC*AA]
#define SMEM_FLOATS (HH * XPAD + HH * LL + 256 + KC * AA)

extern "C" __global__ void __launch_bounds__(NTHREADS, 1)
va_main(const float* __restrict__ lh,
        const float* __restrict__ Wd, const float* __restrict__ bd,
        const float* __restrict__ Wc, const float* __restrict__ bc,
        float* __restrict__ out) {
    extern __shared__ float smem[];
    float* sXt  = smem;                         // [k][row], stride XPAD (even!)
    float* sWc  = smem + HH * XPAD;             // [l*HH + h]
    float* sWc2 = sWc + HH * LL;                // [a*2 + l]
    float* sW   = sWc2 + 256;                   // [kk][128]
    __shared__ int sB[MTILE];

    const int tid  = threadIdx.x;
    const int lane = tid & 31;
    const int warp = tid >> 5;
    const int rg   = lane & 15;                 // rows 2*rg, 2*rg+1
    const int ch   = lane >> 4;                 // col half
    const int cg   = 2 * warp + ch;             // colgroup 0..15
    const int cg8  = cg * 8;                    // 8 output cols

    // stage Wc (classifier) once — covered by first in-loop barrier
    for (int i = tid; i < HH * LL; i += NTHREADS) sWc[i] = Wc[i];

    const int ntiles = g_ntiles;

    for (int t = blockIdx.x; t < ntiles; t += gridDim.x) {
        const int info = g_tiles[t];
        const int v    = info >> 16;
        const int row0 = (info & 0xFFFF) * MTILE;
        const int cnt  = g_counts[v];

        if (tid < MTILE) {
            int gr = row0 + tid;
            sB[tid] = (gr < cnt) ? g_bins[v * BB + gr] : -1;
        }
        __syncthreads();

        // ---- GEMM1 stage-0 weight prefetch (overlaps gather) ----
        const float* Wdv = Wd + (size_t)v * HH * AA;
        float4 pf[16];
        #pragma unroll
        for (int q = 0; q < 16; q++)
            pf[q] = *(const float4*)(Wdv + (size_t)(q * NTHREADS + tid) * 4);

        // ---- gather 32 x rows (t=0) transposed into sXt ----
        for (int idx = tid; idx < MTILE * (HH / 4); idx += NTHREADS) {
            int r  = idx & 31;
            int k4 = idx >> 5;
            int b  = sB[r];
            float4 val = make_float4(0.f, 0.f, 0.f, 0.f);
            if (b >= 0)
                val = *(const float4*)(lh + (size_t)b * TT * HH + k4 * 4);
            sXt[(k4 * 4 + 0) * XPAD + r] = val.x;
            sXt[(k4 * 4 + 1) * XPAD + r] = val.y;
            sXt[(k4 * 4 + 2) * XPAD + r] = val.z;
            sXt[(k4 * 4 + 3) * XPAD + r] = val.w;
        }

        u64t acc1[2][4];
        #pragma unroll
        for (int i = 0; i < 2; i++)
            #pragma unroll
            for (int j = 0; j < 4; j++) acc1[i][j] = 0ull;

        __syncthreads();   // sXt ready; sW free

        // ============ GEMM1: H[32][128] = X[32][768] @ Wd[v] ============
        for (int k0 = 0; k0 < HH; k0 += KC) {
            #pragma unroll
            for (int q = 0; q < 16; q++)
                *(float4*)(sW + (q * NTHREADS + tid) * 4) = pf[q];
            __syncthreads();
            if (k0 + KC < HH) {
                const float* src = Wdv + (size_t)(k0 + KC) * AA;
                #pragma unroll
                for (int q = 0; q < 16; q++)
                    pf[q] = *(const float4*)(src + (size_t)(q * NTHREADS + tid) * 4);
            }
            #pragma unroll 4
            for (int kk = 0; kk < KC; kk++) {
                float2 a2 = *(const float2*)(sXt + (k0 + kk) * XPAD + 2 * rg);
                double2 B0 = *(const double2*)(sW + kk * AA + cg8);
                double2 B1 = *(const double2*)(sW + kk * AA + cg8 + 4);
                u64t a0 = dup2(a2.x), a1 = dup2(a2.y);
                u64t b0 = __double_as_longlong(B0.x);
                u64t b1 = __double_as_longlong(B0.y);
                u64t b2 = __double_as_longlong(B1.x);
                u64t b3 = __double_as_longlong(B1.y);
                acc1[0][0] = fma2(a0, b0, acc1[0][0]);
                acc1[0][1] = fma2(a0, b1, acc1[0][1]);
                acc1[0][2] = fma2(a0, b2, acc1[0][2]);
                acc1[0][3] = fma2(a0, b3, acc1[0][3]);
                acc1[1][0] = fma2(a1, b0, acc1[1][0]);
                acc1[1][1] = fma2(a1, b1, acc1[1][1]);
                acc1[1][2] = fma2(a1, b2, acc1[1][2]);
                acc1[1][3] = fma2(a1, b3, acc1[1][3]);
            }
            __syncthreads();
        }

        // ---- stage this variety's folded head Wc2[v] (256 floats) ----
        sWc2[tid] = g_Wc2[v * AA * LL + tid];

        // ---- bias + gelu (registers) ----
        float hv[2][8];
        {
            const float* bdv = bd + v * AA;
            #pragma unroll
            for (int i = 0; i < 2; i++)
                #pragma unroll
                for (int j2 = 0; j2 < 4; j2++) {
                    float2 f = upk(acc1[i][j2]);
                    hv[i][2 * j2 + 0] = gelu_tanh(f.x + __ldg(bdv + cg8 + 2 * j2 + 0));
                    hv[i][2 * j2 + 1] = gelu_tanh(f.y + __ldg(bdv + cg8 + 2 * j2 + 1));
                }
        }

        // ---- xc partials: x @ Wc^T over this thread's 48-col slice ----
        float outacc[2][2];
        outacc[0][0] = outacc[0][1] = outacc[1][0] = outacc[1][1] = 0.f;
        {
            int c0 = cg * 48;
            #pragma unroll 4
            for (int c = c0; c < c0 + 48; c++) {
                float2 xv = *(const float2*)(sXt + c * XPAD + 2 * rg);
                float wc0 = sWc[c];
                float wc1 = sWc[HH + c];
                outacc[0][0] = fmaf(xv.x, wc0, outacc[0][0]);
                outacc[0][1] = fmaf(xv.x, wc1, outacc[0][1]);
                outacc[1][0] = fmaf(xv.y, wc0, outacc[1][0]);
                outacc[1][1] = fmaf(xv.y, wc1, outacc[1][1]);
            }
        }
        __syncthreads();   // sWc2 ready

        // ---- folded head: out += h @ Wc2[v] over this thread's 8 cols ----
        #pragma unroll
        for (int j = 0; j < 8; j++) {
            float w0 = sWc2[(cg8 + j) * 2 + 0];
            float w1 = sWc2[(cg8 + j) * 2 + 1];
            outacc[0][0] = fmaf(hv[0][j], w0, outacc[0][0]);
            outacc[0][1] = fmaf(hv[0][j], w1, outacc[0][1]);
            outacc[1][0] = fmaf(hv[1][j], w0, outacc[1][0]);
            outacc[1][1] = fmaf(hv[1][j], w1, outacc[1][1]);
        }

        // ---- reduce over 16 colgroups ----
        #pragma unroll
        for (int i = 0; i < 2; i++)
            #pragma unroll
            for (int l = 0; l < 2; l++)
                outacc[i][l] += __shfl_xor_sync(0xFFFFFFFFu, outacc[i][l], 16);

        float* sRed = sW;   // free now
        if (ch == 0) {
            #pragma unroll
            for (int i = 0; i < 2; i++)
                #pragma unroll
                for (int l = 0; l < 2; l++)
                    sRed[((warp * 16 + rg) * 2 + i) * 2 + l] = outacc[i][l];
        }
        __syncthreads();
        if (tid < MTILE * LL) {
            int row = tid >> 1;
            int l   = tid & 1;
            float s = __ldg(bc + l) + g_buc[v * 2 + l];
            #pragma unroll
            for (int w = 0; w < 8; w++)
                s += sRed[((w * 16 + (row >> 1)) * 2 + (row & 1)) * 2 + l];
            int b = sB[row];
            if (b >= 0) out[b * LL + l] = s;
        }
        __syncthreads();
    }
}

extern "C" void kernel_launch(void* const* d_in, const int* in_sizes, int n_in,
                              void* d_out, int out_size) {
    const float* lh   = (const float*)d_in[0];
    const int*   vids = (const int*)d_in[2];
    const float* Wd   = (const float*)d_in[3];
    const float* bd   = (const float*)d_in[4];
    const float* Wu   = (const float*)d_in[5];
    const float* bu   = (const float*)d_in[6];
    const float* Wc   = (const float*)d_in[7];
    const float* bc   = (const float*)d_in[8];
    float* out = (float*)d_out;

    size_t smem_bytes = SMEM_FLOATS * sizeof(float);
    cudaFuncSetAttribute(va_main, cudaFuncAttributeMaxDynamicSharedMemorySize,
                         (int)smem_bytes);

    va_zero_counts<<<1, 32>>>();
    va_bin<<<BB / 256, 256>>>(vids);
    va_build_tiles<<<1, 32>>>();
    va_fold<<<VV, 256>>>(Wu, bu, Wc);
    va_main<<<148, NTHREADS, smem_bytes>>>(lh, Wd, bd, Wc, bc, out);
}

// round 7
// speedup vs baseline: 1.7187x; 1.4418x over previous
#include <cuda_runtime.h>

#define BB 4096
#define TT 16
#define HH 768
#define AA 128
#define VV 16
#define LL 2
#define MTILE 32
#define KC 128
#define XPAD 34
#define NTHREADS 256
#define MAXTILES 160

// ---- device-global scratch ----
__device__ int g_counts[VV];
__device__ int g_bins[VV * BB];
__device__ int g_ntiles;
__device__ int g_tiles[MAXTILES];
__device__ float g_Wc2[VV * AA * LL];   // [v][a][l] = sum_h Wu[v][a][h] * Wc[l][h]
__device__ float g_buc[VV * LL];        // [v][l]    = sum_h bu[v][h]    * Wc[l][h]

__global__ void va_zero_counts() {
    if (threadIdx.x < VV) g_counts[threadIdx.x] = 0;
}

__global__ void va_bin(const int* __restrict__ vids) {
    int b = blockIdx.x * blockDim.x + threadIdx.x;
    if (b < BB) {
        int v = vids[b];
        int slot = atomicAdd(&g_counts[v], 1);
        g_bins[v * BB + slot] = b;
    }
}

__global__ void va_build_tiles() {
    if (threadIdx.x == 0) {
        int t = 0;
        for (int v = 0; v < VV; v++) {
            int c = g_counts[v];
            for (int r0 = 0; r0 < c; r0 += MTILE)
                g_tiles[t++] = (v << 16) | (r0 / MTILE);
        }
        g_ntiles = t;
    }
}

// ---- fold the classifier through Wu:  Wc2[v] = Wu[v] @ Wc^T ----
// grid (VV, 16): one block per (variety, 8-row segment); one warp per Wu row.
__global__ void __launch_bounds__(256, 4)
va_fold(const float* __restrict__ Wu,
        const float* __restrict__ bu,
        const float* __restrict__ Wc) {
    __shared__ float sWc[HH * LL];
    const int v    = blockIdx.x;
    const int seg  = blockIdx.y;
    const int tid  = threadIdx.x;
    const int warp = tid >> 5;
    const int lane = tid & 31;

    for (int i = tid; i < HH * LL; i += 256) sWc[i] = Wc[i];
    __syncthreads();

    const int a = seg * 8 + warp;
    const float* row = Wu + ((size_t)v * AA + a) * HH;
    float s0 = 0.f, s1 = 0.f;
    #pragma unroll
    for (int it = 0; it < 6; it++) {
        int h = it * 128 + lane * 4;
        float4 w = *(const float4*)(row + h);
        s0 = fmaf(w.x, sWc[h + 0], s0);
        s0 = fmaf(w.y, sWc[h + 1], s0);
        s0 = fmaf(w.z, sWc[h + 2], s0);
        s0 = fmaf(w.w, sWc[h + 3], s0);
        s1 = fmaf(w.x, sWc[HH + h + 0], s1);
        s1 = fmaf(w.y, sWc[HH + h + 1], s1);
        s1 = fmaf(w.z, sWc[HH + h + 2], s1);
        s1 = fmaf(w.w, sWc[HH + h + 3], s1);
    }
    #pragma unroll
    for (int off = 16; off; off >>= 1) {
        s0 += __shfl_xor_sync(0xFFFFFFFFu, s0, off);
        s1 += __shfl_xor_sync(0xFFFFFFFFu, s1, off);
    }
    if (lane == 0) {
        g_Wc2[(v * AA + a) * 2 + 0] = s0;
        g_Wc2[(v * AA + a) * 2 + 1] = s1;
    }

    // bias fold: one warp per variety
    if (seg == 0 && warp == 0) {
        const float* brow = bu + (size_t)v * HH;
        float t0 = 0.f, t1 = 0.f;
        #pragma unroll
        for (int it = 0; it < 6; it++) {
            int h = it * 128 + lane * 4;
            float4 w = *(const float4*)(brow + h);
            t0 = fmaf(w.x, sWc[h + 0], t0);
            t0 = fmaf(w.y, sWc[h + 1], t0);
            t0 = fmaf(w.z, sWc[h + 2], t0);
            t0 = fmaf(w.w, sWc[h + 3], t0);
            t1 = fmaf(w.x, sWc[HH + h + 0], t1);
            t1 = fmaf(w.y, sWc[HH + h + 1], t1);
            t1 = fmaf(w.z, sWc[HH + h + 2], t1);
            t1 = fmaf(w.w, sWc[HH + h + 3], t1);
        }
        #pragma unroll
        for (int off = 16; off; off >>= 1) {
            t0 += __shfl_xor_sync(0xFFFFFFFFu, t0, off);
            t1 += __shfl_xor_sync(0xFFFFFFFFu, t1, off);
        }
        if (lane == 0) {
            g_buc[v * 2 + 0] = t0;
            g_buc[v * 2 + 1] = t1;
        }
    }
}

// ---- f32x2 packed-FMA helpers ----
typedef unsigned long long u64t;

__device__ __forceinline__ u64t dup2(float x) {
    u64t r;
    asm("mov.b64 %0, {%1, %1};" : "=l"(r) : "f"(x));
    return r;
}
__device__ __forceinline__ u64t fma2(u64t a, u64t b, u64t c) {
    u64t d;
    asm("fma.rn.f32x2 %0, %1, %2, %3;" : "=l"(d) : "l"(a), "l"(b), "l"(c));
    return d;
}
__device__ __forceinline__ float2 upk(u64t d) {
    float2 f;
    asm("mov.b64 {%0, %1}, %2;" : "=f"(f.x), "=f"(f.y) : "l"(d));
    return f;
}

__device__ __forceinline__ float gelu_tanh(float x) {
    float x3 = x * x * x;
    float t = tanhf(0.7978845608028654f * (x + 0.044715f * x3));
    return 0.5f * x * (1.0f + t);
}

// smem: sXt[HH][XPAD] + sWc[HH*LL] + sWc2[256] + sW[KC*AA]
#define SMEM_FLOATS (HH * XPAD + HH * LL + 256 + KC * AA)

extern "C" __global__ void __launch_bounds__(NTHREADS, 1)
va_main(const float* __restrict__ lh,
        const float* __restrict__ Wd, const float* __restrict__ bd,
        const float* __restrict__ Wc, const float* __restrict__ bc,
        float* __restrict__ out) {
    extern __shared__ float smem[];
    float* sXt  = smem;                         // [k][row], stride XPAD (even!)
    float* sWc  = smem + HH * XPAD;             // [l*HH + h]
    float* sWc2 = sWc + HH * LL;                // [a*2 + l]
    float* sW   = sWc2 + 256;                   // [kk][128]
    __shared__ int sB[MTILE];

    const int tid  = threadIdx.x;
    const int lane = tid & 31;
    const int warp = tid >> 5;
    const int rg   = lane & 15;                 // rows 2*rg, 2*rg+1
    const int ch   = lane >> 4;                 // col half
    const int cg   = 2 * warp + ch;             // colgroup 0..15
    const int cg8  = cg * 8;                    // 8 output cols

    // stage Wc (classifier) once — covered by first in-loop barrier
    for (int i = tid; i < HH * LL; i += NTHREADS) sWc[i] = Wc[i];

    const int ntiles = g_ntiles;

    for (int t = blockIdx.x; t < ntiles; t += gridDim.x) {
        const int info = g_tiles[t];
        const int v    = info >> 16;
        const int row0 = (info & 0xFFFF) * MTILE;
        const int cnt  = g_counts[v];

        if (tid < MTILE) {
            int gr = row0 + tid;
            sB[tid] = (gr < cnt) ? g_bins[v * BB + gr] : -1;
        }
        __syncthreads();

        // ---- GEMM1 stage-0 weight prefetch (overlaps gather) ----
        const float* Wdv = Wd + (size_t)v * HH * AA;
        float4 pf[16];
        #pragma unroll
        for (int q = 0; q < 16; q++)
            pf[q] = *(const float4*)(Wdv + (size_t)(q * NTHREADS + tid) * 4);

        // ---- gather 32 x rows (t=0) transposed into sXt ----
        for (int idx = tid; idx < MTILE * (HH / 4); idx += NTHREADS) {
            int r  = idx & 31;
            int k4 = idx >> 5;
            int b  = sB[r];
            float4 val = make_float4(0.f, 0.f, 0.f, 0.f);
            if (b >= 0)
                val = *(const float4*)(lh + (size_t)b * TT * HH + k4 * 4);
            sXt[(k4 * 4 + 0) * XPAD + r] = val.x;
            sXt[(k4 * 4 + 1) * XPAD + r] = val.y;
            sXt[(k4 * 4 + 2) * XPAD + r] = val.z;
            sXt[(k4 * 4 + 3) * XPAD + r] = val.w;
        }

        u64t acc1[2][4];
        #pragma unroll
        for (int i = 0; i < 2; i++)
            #pragma unroll
            for (int j = 0; j < 4; j++) acc1[i][j] = 0ull;

        __syncthreads();   // sXt ready; sW free

        // ============ GEMM1: H[32][128] = X[32][768] @ Wd[v] ============
        for (int k0 = 0; k0 < HH; k0 += KC) {
            #pragma unroll
            for (int q = 0; q < 16; q++)
                *(float4*)(sW + (q * NTHREADS + tid) * 4) = pf[q];
            __syncthreads();
            if (k0 + KC < HH) {
                const float* src = Wdv + (size_t)(k0 + KC) * AA;
                #pragma unroll
                for (int q = 0; q < 16; q++)
                    pf[q] = *(const float4*)(src + (size_t)(q * NTHREADS + tid) * 4);
            }
            #pragma unroll 4
            for (int kk = 0; kk < KC; kk++) {
                float2 a2 = *(const float2*)(sXt + (k0 + kk) * XPAD + 2 * rg);
                double2 B0 = *(const double2*)(sW + kk * AA + cg8);
                double2 B1 = *(const double2*)(sW + kk * AA + cg8 + 4);
                u64t a0 = dup2(a2.x), a1 = dup2(a2.y);
                u64t b0 = __double_as_longlong(B0.x);
                u64t b1 = __double_as_longlong(B0.y);
                u64t b2 = __double_as_longlong(B1.x);
                u64t b3 = __double_as_longlong(B1.y);
                acc1[0][0] = fma2(a0, b0, acc1[0][0]);
                acc1[0][1] = fma2(a0, b1, acc1[0][1]);
                acc1[0][2] = fma2(a0, b2, acc1[0][2]);
                acc1[0][3] = fma2(a0, b3, acc1[0][3]);
                acc1[1][0] = fma2(a1, b0, acc1[1][0]);
                acc1[1][1] = fma2(a1, b1, acc1[1][1]);
                acc1[1][2] = fma2(a1, b2, acc1[1][2]);
                acc1[1][3] = fma2(a1, b3, acc1[1][3]);
            }
            __syncthreads();
        }

        // ---- stage this variety's folded head Wc2[v] (256 floats) ----
        sWc2[tid] = g_Wc2[v * AA * LL + tid];

        // ---- bias + gelu (registers) ----
        float hv[2][8];
        {
            const float* bdv = bd + v * AA;
            #pragma unroll
            for (int i = 0; i < 2; i++)
                #pragma unroll
                for (int j2 = 0; j2 < 4; j2++) {
                    float2 f = upk(acc1[i][j2]);
                    hv[i][2 * j2 + 0] = gelu_tanh(f.x + __ldg(bdv + cg8 + 2 * j2 + 0));
                    hv[i][2 * j2 + 1] = gelu_tanh(f.y + __ldg(bdv + cg8 + 2 * j2 + 1));
                }
        }

        // ---- xc partials: x @ Wc^T over this thread's 48-col slice ----
        float outacc[2][2];
        outacc[0][0] = outacc[0][1] = outacc[1][0] = outacc[1][1] = 0.f;
        {
            int c0 = cg * 48;
            #pragma unroll 4
            for (int c = c0; c < c0 + 48; c++) {
                float2 xv = *(const float2*)(sXt + c * XPAD + 2 * rg);
                float wc0 = sWc[c];
                float wc1 = sWc[HH + c];
                outacc[0][0] = fmaf(xv.x, wc0, outacc[0][0]);
                outacc[0][1] = fmaf(xv.x, wc1, outacc[0][1]);
                outacc[1][0] = fmaf(xv.y, wc0, outacc[1][0]);
                outacc[1][1] = fmaf(xv.y, wc1, outacc[1][1]);
            }
        }
        __syncthreads();   // sWc2 ready

        // ---- folded head: out += h @ Wc2[v] over this thread's 8 cols ----
        #pragma unroll
        for (int j = 0; j < 8; j++) {
            float w0 = sWc2[(cg8 + j) * 2 + 0];
            float w1 = sWc2[(cg8 + j) * 2 + 1];
            outacc[0][0] = fmaf(hv[0][j], w0, outacc[0][0]);
            outacc[0][1] = fmaf(hv[0][j], w1, outacc[0][1]);
            outacc[1][0] = fmaf(hv[1][j], w0, outacc[1][0]);
            outacc[1][1] = fmaf(hv[1][j], w1, outacc[1][1]);
        }

        // ---- reduce over 16 colgroups ----
        #pragma unroll
        for (int i = 0; i < 2; i++)
            #pragma unroll
            for (int l = 0; l < 2; l++)
                outacc[i][l] += __shfl_xor_sync(0xFFFFFFFFu, outacc[i][l], 16);

        float* sRed = sW;   // free now
        if (ch == 0) {
            #pragma unroll
            for (int i = 0; i < 2; i++)
                #pragma unroll
                for (int l = 0; l < 2; l++)
                    sRed[((warp * 16 + rg) * 2 + i) * 2 + l] = outacc[i][l];
        }
        __syncthreads();
        if (tid < MTILE * LL) {
            int row = tid >> 1;
            int l   = tid & 1;
            float s = __ldg(bc + l) + g_buc[v * 2 + l];
            #pragma unroll
            for (int w = 0; w < 8; w++)
                s += sRed[((w * 16 + (row >> 1)) * 2 + (row & 1)) * 2 + l];
            int b = sB[row];
            if (b >= 0) out[b * LL + l] = s;
        }
        __syncthreads();
    }
}

extern "C" void kernel_launch(void* const* d_in, const int* in_sizes, int n_in,
                              void* d_out, int out_size) {
    const float* lh   = (const float*)d_in[0];
    const int*   vids = (const int*)d_in[2];
    const float* Wd   = (const float*)d_in[3];
    const float* bd   = (const float*)d_in[4];
    const float* Wu   = (const float*)d_in[5];
    const float* bu   = (const float*)d_in[6];
    const float* Wc   = (const float*)d_in[7];
    const float* bc   = (const float*)d_in[8];
    float* out = (float*)d_out;

    size_t smem_bytes = SMEM_FLOATS * sizeof(float);
    cudaFuncSetAttribute(va_main, cudaFuncAttributeMaxDynamicSharedMemorySize,
                         (int)smem_bytes);

    va_zero_counts<<<1, 32>>>();
    va_bin<<<BB / 256, 256>>>(vids);
    va_build_tiles<<<1, 32>>>();
    va_fold<<<dim3(VV, 16), 256>>>(Wu, bu, Wc);
    va_main<<<148, NTHREADS, smem_bytes>>>(lh, Wd, bd, Wc, bc, out);
}

// round 9
// speedup vs baseline: 1.7782x; 1.0346x over previous
#include <cuda_runtime.h>
#include <cuda_bf16.h>
#include <cstdint>

#define BB 4096
#define TT 16
#define HH 768
#define AA 128
#define VV 16
#define LL 2
#define MTILE 128
#define MAXTILES 64
#define NTH 256
#define KCH 64
#define NCHUNK 12          // 768 / 64
#define STRB 144           // bytes per smem row: 64 bf16 (128B) + 16B pad
#define SA_BYTES (128 * STRB)
#define STAGE (2 * SA_BYTES)
#define DYN_SMEM (3 * STAGE)

// ---------------- device scratch ----------------
__device__ int g_counts[VV];
__device__ int g_bins[VV * BB];
__device__ int g_ntiles;
__device__ int g_tiles[MAXTILES];
__device__ float g_Wc2[VV * AA * LL];
__device__ float g_buc[VV * LL];
__device__ float g_xc[BB * LL];
__device__ __align__(16) __nv_bfloat16 g_xbf16[BB * HH];
__device__ __align__(16) __nv_bfloat16 g_WdT[VV * AA * HH];

// ---------------- PTX helpers (sm_80+ baseline only) ----------------
__device__ __forceinline__ uint32_t smem_to_u32(const void* p) {
    uint32_t a;
    asm("{ .reg .u64 t; cvta.to.shared.u64 t, %1; cvt.u32.u64 %0, t; }"
        : "=r"(a) : "l"(p));
    return a;
}
#define CP_ASYNC16(dst, src) \
    asm volatile("cp.async.cg.shared.global [%0], [%1], 16;" :: "r"(dst), "l"(src) : "memory")
#define CP_COMMIT() asm volatile("cp.async.commit_group;" ::: "memory")
#define CP_WAIT2()  asm volatile("cp.async.wait_group 2;" ::: "memory")
#define CP_WAIT1()  asm volatile("cp.async.wait_group 1;" ::: "memory")
#define CP_WAIT0()  asm volatile("cp.async.wait_group 0;" ::: "memory")

__device__ __forceinline__ void ldsm4(uint32_t* r, uint32_t addr) {
    asm volatile("ldmatrix.sync.aligned.m8n8.x4.shared.b16 {%0,%1,%2,%3}, [%4];"
        : "=r"(r[0]), "=r"(r[1]), "=r"(r[2]), "=r"(r[3]) : "r"(addr));
}
__device__ __forceinline__ void mma16816(float* c, const uint32_t* a, const uint32_t* b) {
    asm volatile(
        "mma.sync.aligned.m16n8k16.row.col.f32.bf16.bf16.f32 "
        "{%0,%1,%2,%3}, {%4,%5,%6,%7}, {%8,%9}, {%0,%1,%2,%3};"
        : "+f"(c[0]), "+f"(c[1]), "+f"(c[2]), "+f"(c[3])
        : "r"(a[0]), "r"(a[1]), "r"(a[2]), "r"(a[3]), "r"(b[0]), "r"(b[1]));
}
__device__ __forceinline__ float gelu_fast(float x) {
    float x3 = x * x * x;
    float arg = 0.7978845608028654f * (x + 0.044715f * x3);
    float t;
    asm("tanh.approx.f32 %0, %1;" : "=f"(t) : "f"(arg));
    return 0.5f * x * (1.0f + t);
}

// ---------------- setup kernels ----------------
__global__ void va_zero_counts() {
    if (threadIdx.x < VV) g_counts[threadIdx.x] = 0;
}

__global__ void va_bin(const int* __restrict__ vids) {
    int b = blockIdx.x * blockDim.x + threadIdx.x;
    if (b < BB) {
        int v = vids[b];
        int slot = atomicAdd(&g_counts[v], 1);
        g_bins[v * BB + slot] = b;
    }
}

__global__ void va_build_tiles() {
    if (threadIdx.x == 0) {
        int t = 0;
        for (int v = 0; v < VV; v++) {
            int c = g_counts[v];
            for (int r0 = 0; r0 < c; r0 += MTILE)
                g_tiles[t++] = (v << 16) | (r0 / MTILE);
        }
        g_ntiles = t;
    }
}

// x (t=0 slice) -> bf16 rows + fp32 xc = x @ Wc^T
__global__ void __launch_bounds__(256, 4)
va_prep_x(const float* __restrict__ lh, const float* __restrict__ Wc) {
    __shared__ float sWc[HH * LL];
    const int tid  = threadIdx.x;
    const int warp = tid >> 5;
    const int lane = tid & 31;
    for (int i = tid; i < HH * LL; i += 256) sWc[i] = Wc[i];
    __syncthreads();

    #pragma unroll
    for (int iter = 0; iter < 2; iter++) {
        int r = blockIdx.x * 16 + warp * 2 + iter;
        const float* src = lh + (size_t)r * TT * HH;
        float s0 = 0.f, s1 = 0.f;
        #pragma unroll
        for (int it = 0; it < 6; it++) {
            int h = it * 128 + lane * 4;
            float4 w = *(const float4*)(src + h);
            s0 = fmaf(w.x, sWc[h + 0], s0);
            s0 = fmaf(w.y, sWc[h + 1], s0);
            s0 = fmaf(w.z, sWc[h + 2], s0);
            s0 = fmaf(w.w, sWc[h + 3], s0);
            s1 = fmaf(w.x, sWc[HH + h + 0], s1);
            s1 = fmaf(w.y, sWc[HH + h + 1], s1);
            s1 = fmaf(w.z, sWc[HH + h + 2], s1);
            s1 = fmaf(w.w, sWc[HH + h + 3], s1);
            __nv_bfloat162 p0 = __floats2bfloat162_rn(w.x, w.y);
            __nv_bfloat162 p1 = __floats2bfloat162_rn(w.z, w.w);
            uint2 pk;
            pk.x = *reinterpret_cast<uint32_t*>(&p0);
            pk.y = *reinterpret_cast<uint32_t*>(&p1);
            *reinterpret_cast<uint2*>(g_xbf16 + (size_t)r * HH + h) = pk;
        }
        #pragma unroll
        for (int off = 16; off; off >>= 1) {
            s0 += __shfl_xor_sync(0xFFFFFFFFu, s0, off);
            s1 += __shfl_xor_sync(0xFFFFFFFFu, s1, off);
        }
        if (lane == 0) {
            g_xc[r * 2 + 0] = s0;
            g_xc[r * 2 + 1] = s1;
        }
    }
}

// Wd[v][k][n] fp32 -> WdT[v][n][k] bf16 (tile transpose via smem)
__global__ void __launch_bounds__(256, 2)
va_wdt(const float* __restrict__ Wd) {
    __shared__ __nv_bfloat16 s[128 * 130];
    const int v  = blockIdx.x;
    const int k0 = blockIdx.y * 128;
    const int tid = threadIdx.x;

    const float* base = Wd + (size_t)v * HH * AA + (size_t)k0 * AA;
    #pragma unroll
    for (int i = 0; i < 16; i++) {
        int idx4 = tid + i * 256;
        int k  = idx4 >> 5;
        int n4 = (idx4 & 31) * 4;
        float4 w = *(const float4*)(base + k * AA + n4);
        __nv_bfloat162 p0 = __floats2bfloat162_rn(w.x, w.y);
        __nv_bfloat162 p1 = __floats2bfloat162_rn(w.z, w.w);
        *reinterpret_cast<__nv_bfloat162*>(&s[k * 130 + n4])     = p0;
        *reinterpret_cast<__nv_bfloat162*>(&s[k * 130 + n4 + 2]) = p1;
    }
    __syncthreads();

    const int n = tid >> 1;
    const int khalf = tid & 1;
    #pragma unroll
    for (int g = 0; g < 8; g++) {
        __nv_bfloat16 tmp[8];
        #pragma unroll
        for (int e = 0; e < 8; e++) {
            int k = khalf * 64 + g * 8 + e;
            tmp[e] = s[k * 130 + n];
        }
        *reinterpret_cast<uint4*>(g_WdT + ((size_t)v * AA + n) * HH + k0 + khalf * 64 + g * 8) =
            *reinterpret_cast<uint4*>(tmp);
    }
}

// Wc2[v] = Wu[v] @ Wc^T ; buc[v] = bu[v] @ Wc^T
__global__ void __launch_bounds__(256, 4)
va_fold(const float* __restrict__ Wu, const float* __restrict__ bu,
        const float* __restrict__ Wc) {
    __shared__ float sWc[HH * LL];
    const int v    = blockIdx.x;
    const int seg  = blockIdx.y;
    const int tid  = threadIdx.x;
    const int warp = tid >> 5;
    const int lane = tid & 31;

    for (int i = tid; i < HH * LL; i += 256) sWc[i] = Wc[i];
    __syncthreads();

    const int a = seg * 8 + warp;
    const float* row = Wu + ((size_t)v * AA + a) * HH;
    float s0 = 0.f, s1 = 0.f;
    #pragma unroll
    for (int it = 0; it < 6; it++) {
        int h = it * 128 + lane * 4;
        float4 w = *(const float4*)(row + h);
        s0 = fmaf(w.x, sWc[h + 0], s0);
        s0 = fmaf(w.y, sWc[h + 1], s0);
        s0 = fmaf(w.z, sWc[h + 2], s0);
        s0 = fmaf(w.w, sWc[h + 3], s0);
        s1 = fmaf(w.x, sWc[HH + h + 0], s1);
        s1 = fmaf(w.y, sWc[HH + h + 1], s1);
        s1 = fmaf(w.z, sWc[HH + h + 2], s1);
        s1 = fmaf(w.w, sWc[HH + h + 3], s1);
    }
    #pragma unroll
    for (int off = 16; off; off >>= 1) {
        s0 += __shfl_xor_sync(0xFFFFFFFFu, s0, off);
        s1 += __shfl_xor_sync(0xFFFFFFFFu, s1, off);
    }
    if (lane == 0) {
        g_Wc2[(v * AA + a) * 2 + 0] = s0;
        g_Wc2[(v * AA + a) * 2 + 1] = s1;
    }
    if (seg == 0 && warp == 0) {
        const float* brow = bu + (size_t)v * HH;
        float t0 = 0.f, t1 = 0.f;
        #pragma unroll
        for (int it = 0; it < 6; it++) {
            int h = it * 128 + lane * 4;
            float4 w = *(const float4*)(brow + h);
            t0 = fmaf(w.x, sWc[h + 0], t0);
            t0 = fmaf(w.y, sWc[h + 1], t0);
            t0 = fmaf(w.z, sWc[h + 2], t0);
            t0 = fmaf(w.w, sWc[h + 3], t0);
            t1 = fmaf(w.x, sWc[HH + h + 0], t1);
            t1 = fmaf(w.y, sWc[HH + h + 1], t1);
            t1 = fmaf(w.z, sWc[HH + h + 2], t1);
            t1 = fmaf(w.w, sWc[HH + h + 3], t1);
        }
        #pragma unroll
        for (int off = 16; off; off >>= 1) {
            t0 += __shfl_xor_sync(0xFFFFFFFFu, t0, off);
            t1 += __shfl_xor_sync(0xFFFFFFFFu, t1, off);
        }
        if (lane == 0) {
            g_buc[v * 2 + 0] = t0;
            g_buc[v * 2 + 1] = t1;
        }
    }
}

// ---------------- main mma.sync kernel ----------------
extern "C" __global__ void __launch_bounds__(NTH, 1)
va_main_mma(const float* __restrict__ bd, const float* __restrict__ bc,
            float* __restrict__ out) {
    extern __shared__ char dsm[];
    __shared__ int   sB[128];
    __shared__ float sBd[128];
    __shared__ float sWc2[256];
    __shared__ float sRed[2 * 128 * 2];

    const int tid  = threadIdx.x;
    const int warp = tid >> 5;
    const int lane = tid & 31;
    const int wm   = warp & 3;    // row group: 32*wm
    const int wn   = warp >> 2;   // col group: 64*wn

    const int t = blockIdx.x;
    if (t >= g_ntiles) return;
    const int info = g_tiles[t];
    const int vv   = info >> 16;
    const int row0 = (info & 0xFFFF) * MTILE;
    const int cnt  = g_counts[vv];

    if (tid < 128) {
        int gr = row0 + tid;
        sB[tid]  = (gr < cnt) ? g_bins[vv * BB + gr] : -1;
        sBd[tid] = bd[vv * AA + tid];
    }
    sWc2[tid] = g_Wc2[vv * AA * LL + tid];
    __syncthreads();

    const uint32_t dynb = smem_to_u32(dsm);

    // per-thread cp.async sources/dest offsets (4 A rows + 4 B rows)
    const __nv_bfloat16* aSrc[4];
    const __nv_bfloat16* bSrc[4];
    uint32_t dA[4], dB[4];
    #pragma unroll
    for (int i = 0; i < 4; i++) {
        int idx = tid * 4 + i;        // 0..1023
        int row = idx >> 3;
        int seg = idx & 7;
        int brow = sB[row];
        if (brow < 0) brow = 0;       // garbage rows never stored
        aSrc[i] = g_xbf16 + (size_t)brow * HH + seg * 8;
        bSrc[i] = g_WdT + ((size_t)vv * AA + row) * HH + seg * 8;
        dA[i] = (uint32_t)(row * STRB + seg * 16);
        dB[i] = (uint32_t)(SA_BYTES + row * STRB + seg * 16);
    }

    // ldmatrix per-thread base offsets
    uint32_t aOff[2], bOff[4];
    #pragma unroll
    for (int mf = 0; mf < 2; mf++)
        aOff[mf] = (uint32_t)((32 * wm + 16 * mf + ((lane >> 3) & 1) * 8 + (lane & 7)) * STRB
                              + (lane >> 4) * 16);
    #pragma unroll
    for (int p = 0; p < 4; p++)
        bOff[p] = (uint32_t)(SA_BYTES
                              + (64 * wn + 16 * p + (lane >> 4) * 8 + (lane & 7)) * STRB
                              + ((lane >> 3) & 1) * 16);

    float acc[2][8][4];
    #pragma unroll
    for (int mf = 0; mf < 2; mf++)
        #pragma unroll
        for (int nf = 0; nf < 8; nf++)
            #pragma unroll
            for (int e = 0; e < 4; e++) acc[mf][nf][e] = 0.f;

    // ---- 3-stage cp.async pipeline over 12 K-chunks of 64 ----
    {
        uint32_t base0 = dynb;               // chunk 0 -> stage 0
        #pragma unroll
        for (int i = 0; i < 4; i++) {
            CP_ASYNC16(base0 + dA[i], aSrc[i]);
            CP_ASYNC16(base0 + dB[i], bSrc[i]);
        }
        CP_COMMIT();
        uint32_t base1 = dynb + STAGE;       // chunk 1 -> stage 1
        #pragma unroll
        for (int i = 0; i < 4; i++) {
            CP_ASYNC16(base1 + dA[i], aSrc[i] + KCH);
            CP_ASYNC16(base1 + dB[i], bSrc[i] + KCH);
        }
        CP_COMMIT();
    }

    int stage_c = 0;                         // (c) % 3
    int stage_n = 2;                         // (c+2) % 3
    for (int c = 0; c < NCHUNK; c++) {
        if (c + 2 < NCHUNK) {
            uint32_t base = dynb + stage_n * STAGE;
            const int koff = (c + 2) * KCH;
            #pragma unroll
            for (int i = 0; i < 4; i++) {
                CP_ASYNC16(base + dA[i], aSrc[i] + koff);
                CP_ASYNC16(base + dB[i], bSrc[i] + koff);
            }
            CP_COMMIT();
            CP_WAIT2();
        } else if (c + 1 < NCHUNK) {
            CP_WAIT1();
        } else {
            CP_WAIT0();
        }
        __syncthreads();

        const uint32_t base = dynb + stage_c * STAGE;
        #pragma unroll
        for (int step = 0; step < 4; step++) {
            const uint32_t kb = step * 32;
            uint32_t af[2][4], bf[4][4];
            ldsm4(af[0], base + aOff[0] + kb);
            ldsm4(af[1], base + aOff[1] + kb);
            #pragma unroll
            for (int p = 0; p < 4; p++)
                ldsm4(bf[p], base + bOff[p] + kb);
            #pragma unroll
            for (int mf = 0; mf < 2; mf++)
                #pragma unroll
                for (int p = 0; p < 4; p++) {
                    mma16816(acc[mf][2 * p + 0], af[mf], &bf[p][0]);
                    mma16816(acc[mf][2 * p + 1], af[mf], &bf[p][2]);
                }
        }
        __syncthreads();

        stage_c = (stage_c == 2) ? 0 : stage_c + 1;
        stage_n = (stage_n == 2) ? 0 : stage_n + 1;
    }

    // ---- epilogue: gelu + folded head, reduce ----
    float rp[2][2][2];   // [mf][half][l]
    #pragma unroll
    for (int mf = 0; mf < 2; mf++)
        #pragma unroll
        for (int hh = 0; hh < 2; hh++) { rp[mf][hh][0] = 0.f; rp[mf][hh][1] = 0.f; }

    #pragma unroll
    for (int mf = 0; mf < 2; mf++)
        #pragma unroll
        for (int nf = 0; nf < 8; nf++) {
            int col0 = 64 * wn + 8 * nf + 2 * (lane & 3);
            #pragma unroll
            for (int e = 0; e < 4; e++) {
                int col  = col0 + (e & 1);
                int hh   = e >> 1;
                float h  = gelu_fast(acc[mf][nf][e] + sBd[col]);
                rp[mf][hh][0] = fmaf(h, sWc2[col * 2 + 0], rp[mf][hh][0]);
                rp[mf][hh][1] = fmaf(h, sWc2[col * 2 + 1], rp[mf][hh][1]);
            }
        }

    #pragma unroll
    for (int mf = 0; mf < 2; mf++)
        #pragma unroll
        for (int hh = 0; hh < 2; hh++)
            #pragma unroll
            for (int l = 0; l < 2; l++) {
                float s = rp[mf][hh][l];
                s += __shfl_xor_sync(0xFFFFFFFFu, s, 1);
                s += __shfl_xor_sync(0xFFFFFFFFu, s, 2);
                rp[mf][hh][l] = s;
            }

    if ((lane & 3) == 0) {
        int rbase = 32 * wm + (lane >> 2);
        #pragma unroll
        for (int mf = 0; mf < 2; mf++)
            #pragma unroll
            for (int hh = 0; hh < 2; hh++) {
                int row = rbase + 16 * mf + 8 * hh;
                sRed[(wn * 128 + row) * 2 + 0] = rp[mf][hh][0];
                sRed[(wn * 128 + row) * 2 + 1] = rp[mf][hh][1];
            }
    }
    __syncthreads();

    {
        int row = tid >> 1;
        int l   = tid & 1;
        int b   = sB[row];
        if (b >= 0)
            out[b * 2 + l] = g_xc[b * 2 + l]
                           + sRed[row * 2 + l] + sRed[(128 + row) * 2 + l]
                           + g_buc[vv * 2 + l] + __ldg(bc + l);
    }
}

extern "C" void kernel_launch(void* const* d_in, const int* in_sizes, int n_in,
                              void* d_out, int out_size) {
    const float* lh   = (const float*)d_in[0];
    const int*   vids = (const int*)d_in[2];
    const float* Wd   = (const float*)d_in[3];
    const float* bd   = (const float*)d_in[4];
    const float* Wu   = (const float*)d_in[5];
    const float* bu   = (const float*)d_in[6];
    const float* Wc   = (const float*)d_in[7];
    const float* bc   = (const float*)d_in[8];
    float* out = (float*)d_out;

    cudaFuncSetAttribute(va_main_mma, cudaFuncAttributeMaxDynamicSharedMemorySize, DYN_SMEM);

    va_zero_counts<<<1, 32>>>();
    va_bin<<<BB / 256, 256>>>(vids);
    va_build_tiles<<<1, 32>>>();
    va_prep_x<<<BB / 16, 256>>>(lh, Wc);
    va_wdt<<<dim3(VV, HH / 128), 256>>>(Wd);
    va_fold<<<dim3(VV, 16), 256>>>(Wu, bu, Wc);
    va_main_mma<<<MAXTILES, NTH, DYN_SMEM>>>(bd, bc, out);
}